// round 14
// baseline (speedup 1.0000x reference)
#include <cuda_runtime.h>
#include <cuda_fp16.h>
#include <cuda_bf16.h>

#define MAXN 100000
#define MAXE 3200000
#define CHUNK 2048
#define MAXNB ((MAXN + CHUNK - 1) / CHUNK)
#define NCHUNK 4

// Scratch (device globals; allocation is forbidden)
__device__ __half g_hsc[MAXN * 128];   // fp16(hidden * rsqrt(outdeg))
__device__ __half g_aggh[MAXN * 128];  // fp16(rsin * sum hsc[src])
__device__ __half g_H23h[MAXN * 256];  // fp16(hidden @ W_h[:,128:384]) -> [h2 | h3]
__device__ __half g_WhT[256 * 128];    // fp16(W_h[:,128:384])^T : [c][k]
__device__ __half g_WcT[256 * 128];    // fp16(Wc)^T phys-interleaved : [2c+q][k]
__device__ int    g_outdeg[MAXN];
__device__ int    g_indeg[MAXN];
__device__ int    g_rowptr[MAXN + 1];
__device__ int    g_cursor[MAXN];
__device__ int    g_csr[MAXE];
__device__ int    g_bsum[MAXNB];

typedef unsigned int uint;

__device__ __forceinline__ void mma16816(float4& c, uint a0, uint a1, uint a2, uint a3,
                                         uint b0, uint b1) {
    asm volatile(
        "mma.sync.aligned.m16n8k16.row.col.f32.f16.f16.f32 "
        "{%0,%1,%2,%3}, {%4,%5,%6,%7}, {%8,%9}, {%0,%1,%2,%3};"
        : "+f"(c.x), "+f"(c.y), "+f"(c.z), "+f"(c.w)
        : "r"(a0), "r"(a1), "r"(a2), "r"(a3), "r"(b0), "r"(b1));
}

// ---------------------------------------------------------------------------
__global__ void zero_deg_kernel(int n) {
    int i = blockIdx.x * blockDim.x + threadIdx.x;
    if (i < n) { g_outdeg[i] = 0; g_indeg[i] = 0; }
}

// WhT[c][k] = fp16(W_h[k][128+c])
__global__ void wht_prep_kernel(const float* __restrict__ W_h) {
    int k = blockIdx.x;     // 0..127
    int c = threadIdx.x;    // 0..255
    g_WhT[(size_t)c * 128 + k] = __float2half(W_h[(size_t)k * 384 + 128 + c]);
}

// WcT[phys][k] = fp16( (W_h[:,0:128] @ W_hf)[k][j] ), phys interleaves f1/f2
__global__ __launch_bounds__(256) void wc_kernel(const float* __restrict__ W_h,
                                                 const float* __restrict__ W_hf) {
    __shared__ float row[128];
    int k = blockIdx.x;
    int j = threadIdx.x;
    if (j < 128) row[j] = W_h[(size_t)k * 384 + j];
    __syncthreads();
    float acc = 0.f;
#pragma unroll 8
    for (int m = 0; m < 128; m++) acc = fmaf(row[m], W_hf[(size_t)m * 256 + j], acc);
    int phys = (j < 128) ? (2 * j) : (2 * (j - 128) + 1);
    g_WcT[(size_t)phys * 128 + k] = __float2half(acc);
}

__global__ void outdeg_kernel(const int* __restrict__ src, int e) {
    int i = blockIdx.x * blockDim.x + threadIdx.x;
    int i4 = i * 4;
    if (i4 + 3 < e) {
        int4 s = *reinterpret_cast<const int4*>(&src[i4]);
        atomicAdd(&g_outdeg[s.x], 1); atomicAdd(&g_outdeg[s.y], 1);
        atomicAdd(&g_outdeg[s.z], 1); atomicAdd(&g_outdeg[s.w], 1);
    } else {
        for (int j = i4; j < e; j++) atomicAdd(&g_outdeg[src[j]], 1);
    }
}

__global__ void indeg_kernel(const int* __restrict__ dst, int e) {
    int i = blockIdx.x * blockDim.x + threadIdx.x;
    int i4 = i * 4;
    if (i4 + 3 < e) {
        int4 d = *reinterpret_cast<const int4*>(&dst[i4]);
        atomicAdd(&g_indeg[d.x], 1); atomicAdd(&g_indeg[d.y], 1);
        atomicAdd(&g_indeg[d.z], 1); atomicAdd(&g_indeg[d.w], 1);
    } else {
        for (int j = i4; j < e; j++) atomicAdd(&g_indeg[dst[j]], 1);
    }
}

// --------------------------- scan (2 kernels) ------------------------------
__global__ __launch_bounds__(256) void chunk_reduce_kernel(int n) {
    __shared__ int wsum[8];
    int b = blockIdx.x;
    int base = b * CHUNK;
    int tid = threadIdx.x, lane = tid & 31, wid = tid >> 5;
    int s = 0;
#pragma unroll
    for (int j = 0; j < CHUNK / 256; j++) {
        int idx = base + tid + j * 256;
        s += (idx < n) ? g_indeg[idx] : 0;
    }
#pragma unroll
    for (int o = 16; o > 0; o >>= 1) s += __shfl_down_sync(0xFFFFFFFFu, s, o);
    if (lane == 0) wsum[wid] = s;
    __syncthreads();
    if (tid == 0) {
        int t = 0;
#pragma unroll
        for (int w = 0; w < 8; w++) t += wsum[w];
        g_bsum[b] = t;
    }
}

// chunk_scan computes its own block offset from g_bsum (nb <= 64)
__global__ __launch_bounds__(256) void chunk_scan_kernel(int n, int nb) {
    __shared__ int wsum[8];
    __shared__ int part[2];
    __shared__ int chunk_total;
    int b = blockIdx.x;
    int base = b * CHUNK;
    int tid = threadIdx.x, lane = tid & 31, wid = tid >> 5;

    if (tid < 64) {
        int v = (tid < b) ? g_bsum[tid] : 0;
#pragma unroll
        for (int o = 16; o > 0; o >>= 1) v += __shfl_down_sync(0xFFFFFFFFu, v, o);
        if ((tid & 31) == 0) part[tid >> 5] = v;
    }

    int vals[8];
    int s = 0;
#pragma unroll
    for (int j = 0; j < 8; j++) {
        int idx = base + tid * 8 + j;
        vals[j] = (idx < n) ? g_indeg[idx] : 0;
        s += vals[j];
    }
    int x = s;
#pragma unroll
    for (int o = 1; o < 32; o <<= 1) {
        int y = __shfl_up_sync(0xFFFFFFFFu, x, o);
        if (lane >= o) x += y;
    }
    if (lane == 31) wsum[wid] = x;
    __syncthreads();
    if (tid == 0) {
        int acc = 0;
#pragma unroll
        for (int w = 0; w < 8; w++) { int v = wsum[w]; wsum[w] = acc; acc += v; }
        chunk_total = acc;
    }
    __syncthreads();
    int boff = part[0] + part[1];
    int prefix = boff + wsum[wid] + (x - s);
#pragma unroll
    for (int j = 0; j < 8; j++) {
        int idx = base + tid * 8 + j;
        if (idx < n) { g_rowptr[idx] = prefix; g_cursor[idx] = prefix; }
        prefix += vals[j];
    }
    if (tid == 0 && b == nb - 1) g_rowptr[n] = boff + chunk_total;
}

__global__ void fill_kernel(const int* __restrict__ src, const int* __restrict__ dst, int e) {
    int i = blockIdx.x * blockDim.x + threadIdx.x;
    int i4 = i * 4;
    if (i4 + 3 < e) {
        int4 s = *reinterpret_cast<const int4*>(&src[i4]);
        int4 d = *reinterpret_cast<const int4*>(&dst[i4]);
        g_csr[atomicAdd(&g_cursor[d.x], 1)] = s.x;
        g_csr[atomicAdd(&g_cursor[d.y], 1)] = s.y;
        g_csr[atomicAdd(&g_cursor[d.z], 1)] = s.z;
        g_csr[atomicAdd(&g_cursor[d.w], 1)] = s.w;
    } else {
        for (int j = i4; j < e; j++)
            g_csr[atomicAdd(&g_cursor[dst[j]], 1)] = src[j];
    }
}

// ---------------------------------------------------------------------------
// Gather over node range [node0, node1): one warp per dst node.
__global__ __launch_bounds__(256) void gather_kernel(int node0, int node1) {
    int node = node0 + ((blockIdx.x * blockDim.x + threadIdx.x) >> 5);
    int lane = threadIdx.x & 31;
    if (node >= node1) return;
    int beg = g_rowptr[node];
    int end = g_rowptr[node + 1];

    float4 acc0 = make_float4(0.f, 0.f, 0.f, 0.f);
    float4 acc1 = make_float4(0.f, 0.f, 0.f, 0.f);
    int e = beg;
    for (; e + 3 < end; e += 4) {
        int s0 = g_csr[e], s1 = g_csr[e + 1], s2 = g_csr[e + 2], s3 = g_csr[e + 3];
        uint2 v0 = *reinterpret_cast<const uint2*>(&g_hsc[(size_t)s0 * 128 + lane * 4]);
        uint2 v1 = *reinterpret_cast<const uint2*>(&g_hsc[(size_t)s1 * 128 + lane * 4]);
        uint2 v2 = *reinterpret_cast<const uint2*>(&g_hsc[(size_t)s2 * 128 + lane * 4]);
        uint2 v3 = *reinterpret_cast<const uint2*>(&g_hsc[(size_t)s3 * 128 + lane * 4]);
        float2 a0 = __half22float2(*reinterpret_cast<__half2*>(&v0.x));
        float2 a1 = __half22float2(*reinterpret_cast<__half2*>(&v0.y));
        float2 b0 = __half22float2(*reinterpret_cast<__half2*>(&v1.x));
        float2 b1 = __half22float2(*reinterpret_cast<__half2*>(&v1.y));
        float2 c0 = __half22float2(*reinterpret_cast<__half2*>(&v2.x));
        float2 c1 = __half22float2(*reinterpret_cast<__half2*>(&v2.y));
        float2 d0 = __half22float2(*reinterpret_cast<__half2*>(&v3.x));
        float2 d1 = __half22float2(*reinterpret_cast<__half2*>(&v3.y));
        acc0.x += a0.x + b0.x; acc0.y += a0.y + b0.y;
        acc0.z += a1.x + b1.x; acc0.w += a1.y + b1.y;
        acc1.x += c0.x + d0.x; acc1.y += c0.y + d0.y;
        acc1.z += c1.x + d1.x; acc1.w += c1.y + d1.y;
    }
    for (; e < end; e++) {
        int s0 = g_csr[e];
        uint2 v0 = *reinterpret_cast<const uint2*>(&g_hsc[(size_t)s0 * 128 + lane * 4]);
        float2 a0 = __half22float2(*reinterpret_cast<__half2*>(&v0.x));
        float2 a1 = __half22float2(*reinterpret_cast<__half2*>(&v0.y));
        acc0.x += a0.x; acc0.y += a0.y; acc0.z += a1.x; acc0.w += a1.y;
    }
    float ri = rsqrtf((float)max(end - beg, 1));
    __half2 p0 = __floats2half2_rn((acc0.x + acc1.x) * ri, (acc0.y + acc1.y) * ri);
    __half2 p1 = __floats2half2_rn((acc0.z + acc1.z) * ri, (acc0.w + acc1.w) * ri);
    uint2 st;
    st.x = *reinterpret_cast<uint*>(&p0);
    st.y = *reinterpret_cast<uint*>(&p1);
    *reinterpret_cast<uint2*>(&g_aggh[(size_t)node * 128 + lane * 4]) = st;
}

// ---------------------------------------------------------------------------
// GEMM1 (tensor core): H23h[n,256] = fp16( hidden[n,128] @ W_h[:,128:384] )
// BM=128, BN=128, K=128 in smem. col0==0 blocks also emit hsc during A-fill.
__global__ __launch_bounds__(256) void gemm1_mma(const float* __restrict__ hidden, int n) {
    extern __shared__ char smem[];
    __half (*As)[136] = reinterpret_cast<__half(*)[136]>(smem);
    __half (*Bs)[136] = reinterpret_cast<__half(*)[136]>(smem + 34816);
    __half (*Os)[136] = reinterpret_cast<__half(*)[136]>(smem);  // reuse As post-mma

    int tid = threadIdx.x;
    int row0 = blockIdx.y * 128;
    int col0 = blockIdx.x * 128;

    // A fill (fp32 -> fp16); col0==0 blocks also write hsc = fp16(h * rsout)
#pragma unroll
    for (int i = 0; i < 8; i++) {
        int lin = tid + i * 256;  // 2048 slots of 8 halves
        int r = lin >> 4;
        int kc = (lin & 15) * 8;
        int grow = row0 + r;
        float4 a = make_float4(0.f, 0.f, 0.f, 0.f), b = a;
        if (grow < n) {
            const float4* p = reinterpret_cast<const float4*>(&hidden[(size_t)grow * 128 + kc]);
            a = p[0]; b = p[1];
        }
        __half2 h0 = __floats2half2_rn(a.x, a.y);
        __half2 h1 = __floats2half2_rn(a.z, a.w);
        __half2 h2 = __floats2half2_rn(b.x, b.y);
        __half2 h3 = __floats2half2_rn(b.z, b.w);
        uint4 o;
        o.x = *reinterpret_cast<uint*>(&h0); o.y = *reinterpret_cast<uint*>(&h1);
        o.z = *reinterpret_cast<uint*>(&h2); o.w = *reinterpret_cast<uint*>(&h3);
        *reinterpret_cast<uint4*>(&As[r][kc]) = o;

        if (col0 == 0 && grow < n) {
            float rs = rsqrtf((float)max(g_outdeg[grow], 1));
            __half2 s0 = __floats2half2_rn(a.x * rs, a.y * rs);
            __half2 s1 = __floats2half2_rn(a.z * rs, a.w * rs);
            __half2 s2 = __floats2half2_rn(b.x * rs, b.y * rs);
            __half2 s3 = __floats2half2_rn(b.z * rs, b.w * rs);
            uint4 os;
            os.x = *reinterpret_cast<uint*>(&s0); os.y = *reinterpret_cast<uint*>(&s1);
            os.z = *reinterpret_cast<uint*>(&s2); os.w = *reinterpret_cast<uint*>(&s3);
            *reinterpret_cast<uint4*>(&g_hsc[(size_t)grow * 128 + kc]) = os;
        }
    }
    // B fill (coalesced from transposed fp16 weights)
#pragma unroll
    for (int i = 0; i < 8; i++) {
        int lin = tid + i * 256;
        int r = lin >> 4;
        int kc = (lin & 15) * 8;
        *reinterpret_cast<uint4*>(&Bs[r][kc]) =
            *reinterpret_cast<const uint4*>(&g_WhT[(size_t)(col0 + r) * 128 + kc]);
    }
    __syncthreads();

    int w = tid >> 5, lane = tid & 31;
    int g = lane >> 2, tig = lane & 3;
    int m0 = (w >> 1) * 32;
    int n0 = (w & 1) * 64;

    float4 acc[2][8];
#pragma unroll
    for (int mt = 0; mt < 2; mt++)
#pragma unroll
        for (int j = 0; j < 8; j++) acc[mt][j] = make_float4(0.f, 0.f, 0.f, 0.f);

#pragma unroll
    for (int kt = 0; kt < 128; kt += 16) {
        uint a[2][4];
#pragma unroll
        for (int mt = 0; mt < 2; mt++) {
            int mr = m0 + mt * 16 + g;
            a[mt][0] = *reinterpret_cast<const uint*>(&As[mr][kt + tig * 2]);
            a[mt][1] = *reinterpret_cast<const uint*>(&As[mr + 8][kt + tig * 2]);
            a[mt][2] = *reinterpret_cast<const uint*>(&As[mr][kt + tig * 2 + 8]);
            a[mt][3] = *reinterpret_cast<const uint*>(&As[mr + 8][kt + tig * 2 + 8]);
        }
#pragma unroll
        for (int j = 0; j < 8; j++) {
            int nc = n0 + j * 8 + g;
            uint b0 = *reinterpret_cast<const uint*>(&Bs[nc][kt + tig * 2]);
            uint b1 = *reinterpret_cast<const uint*>(&Bs[nc][kt + tig * 2 + 8]);
            mma16816(acc[0][j], a[0][0], a[0][1], a[0][2], a[0][3], b0, b1);
            mma16816(acc[1][j], a[1][0], a[1][1], a[1][2], a[1][3], b0, b1);
        }
    }
    __syncthreads();

    // Stage results in smem, then coalesced store
#pragma unroll
    for (int mt = 0; mt < 2; mt++) {
#pragma unroll
        for (int j = 0; j < 8; j++) {
            int r1 = m0 + mt * 16 + g;
            int c = n0 + j * 8 + tig * 2;
            __half2 lo = __floats2half2_rn(acc[mt][j].x, acc[mt][j].y);
            __half2 hi = __floats2half2_rn(acc[mt][j].z, acc[mt][j].w);
            *reinterpret_cast<uint*>(&Os[r1][c]) = *reinterpret_cast<uint*>(&lo);
            *reinterpret_cast<uint*>(&Os[r1 + 8][c]) = *reinterpret_cast<uint*>(&hi);
        }
    }
    __syncthreads();
#pragma unroll
    for (int i = 0; i < 8; i++) {
        int lin = tid + i * 256;
        int r = lin >> 4;
        int kc = (lin & 15) * 8;
        if (row0 + r < n)
            *reinterpret_cast<uint4*>(&g_H23h[(size_t)(row0 + r) * 256 + col0 + kc]) =
                *reinterpret_cast<const uint4*>(&Os[r][kc]);
    }
}

// ---------------------------------------------------------------------------
// GEMM2 (tensor core) fused with gated epilogue; smem-staged I/O.
// Processes rows [rbase + blockIdx.y*128, ...). H2s/H3s rows padded to 72 halves.
__global__ __launch_bounds__(256) void gemm2_mma(float* __restrict__ out, int n, int dup,
                                                 int rbase) {
    extern __shared__ char smem[];
    __half (*As)[136] = reinterpret_cast<__half(*)[136]>(smem);
    __half (*Bs)[136] = reinterpret_cast<__half(*)[136]>(smem + 34816);
    __half (*H2s)[72] = reinterpret_cast<__half(*)[72]>(smem + 34816);            // reuse Bs
    __half (*H3s)[72] = reinterpret_cast<__half(*)[72]>(smem + 34816 + 18432);
    float (*Os)[68]   = reinterpret_cast<float(*)[68]>(smem);                     // reuse As

    int tid = threadIdx.x;
    int row0 = rbase + blockIdx.y * 128;
    int col0 = blockIdx.x * 128;  // phys col in [0,256)
    int q0 = col0 >> 1;           // logical col base (0 or 64)

#pragma unroll
    for (int i = 0; i < 8; i++) {
        int lin = tid + i * 256;
        int r = lin >> 4;
        int kc = (lin & 15) * 8;
        uint4 v = make_uint4(0, 0, 0, 0);
        if (row0 + r < n)
            v = *reinterpret_cast<const uint4*>(&g_aggh[(size_t)(row0 + r) * 128 + kc]);
        *reinterpret_cast<uint4*>(&As[r][kc]) = v;
    }
#pragma unroll
    for (int i = 0; i < 8; i++) {
        int lin = tid + i * 256;
        int r = lin >> 4;
        int kc = (lin & 15) * 8;
        *reinterpret_cast<uint4*>(&Bs[r][kc]) =
            *reinterpret_cast<const uint4*>(&g_WcT[(size_t)(col0 + r) * 128 + kc]);
    }
    __syncthreads();

    int w = tid >> 5, lane = tid & 31;
    int g = lane >> 2, tig = lane & 3;
    int m0 = (w >> 1) * 32;
    int n0 = (w & 1) * 64;

    float4 acc[2][8];
#pragma unroll
    for (int mt = 0; mt < 2; mt++)
#pragma unroll
        for (int j = 0; j < 8; j++) acc[mt][j] = make_float4(0.f, 0.f, 0.f, 0.f);

#pragma unroll
    for (int kt = 0; kt < 128; kt += 16) {
        uint a[2][4];
#pragma unroll
        for (int mt = 0; mt < 2; mt++) {
            int mr = m0 + mt * 16 + g;
            a[mt][0] = *reinterpret_cast<const uint*>(&As[mr][kt + tig * 2]);
            a[mt][1] = *reinterpret_cast<const uint*>(&As[mr + 8][kt + tig * 2]);
            a[mt][2] = *reinterpret_cast<const uint*>(&As[mr][kt + tig * 2 + 8]);
            a[mt][3] = *reinterpret_cast<const uint*>(&As[mr + 8][kt + tig * 2 + 8]);
        }
#pragma unroll
        for (int j = 0; j < 8; j++) {
            int nc = n0 + j * 8 + g;
            uint b0 = *reinterpret_cast<const uint*>(&Bs[nc][kt + tig * 2]);
            uint b1 = *reinterpret_cast<const uint*>(&Bs[nc][kt + tig * 2 + 8]);
            mma16816(acc[0][j], a[0][0], a[0][1], a[0][2], a[0][3], b0, b1);
            mma16816(acc[1][j], a[1][0], a[1][1], a[1][2], a[1][3], b0, b1);
        }
    }
    __syncthreads();

    // Load H23 tile (coalesced) into smem: h2/h3 logical cols [q0, q0+64)
#pragma unroll
    for (int i = 0; i < 8; i++) {
        int lin = tid + i * 256;   // 2048 slots of 8 halves
        int a = lin >> 10;         // 0 = h2, 1 = h3
        int rem = lin & 1023;
        int r = rem >> 3;
        int c8 = (rem & 7) * 8;
        uint4 v = make_uint4(0, 0, 0, 0);
        if (row0 + r < n)
            v = *reinterpret_cast<const uint4*>(
                &g_H23h[(size_t)(row0 + r) * 256 + a * 128 + q0 + c8]);
        if (a == 0) *reinterpret_cast<uint4*>(&H2s[r][c8]) = v;
        else        *reinterpret_cast<uint4*>(&H3s[r][c8]) = v;
    }
    __syncthreads();

    // Epilogue into smem: phys pair (acc.x=f1, acc.y=f2) -> logical qloc
#pragma unroll
    for (int mt = 0; mt < 2; mt++) {
#pragma unroll
        for (int j = 0; j < 8; j++) {
            int r1 = m0 + mt * 16 + g;
            int r2 = r1 + 8;
            int qloc = (n0 >> 1) + j * 4 + tig;
            float h2a = __half2float(H2s[r1][qloc]);
            float h3a = __half2float(H3s[r1][qloc]);
            Os[r1][qloc] = h3a + fmaxf(acc[mt][j].x + h2a, 0.f) * acc[mt][j].y;
            float h2b = __half2float(H2s[r2][qloc]);
            float h3b = __half2float(H3s[r2][qloc]);
            Os[r2][qloc] = h3b + fmaxf(acc[mt][j].z + h2b, 0.f) * acc[mt][j].w;
        }
    }
    __syncthreads();

    // Coalesced store of 128 x 64 fp32 tile (+ duplicate half)
    size_t ndup = (size_t)n * 128;
#pragma unroll
    for (int i = 0; i < 8; i++) {
        int lin = tid + i * 256;   // 2048 float4 slots
        int r = lin >> 4;
        int c4 = (lin & 15) * 4;
        if (row0 + r < n) {
            float4 v = *reinterpret_cast<const float4*>(&Os[r][c4]);
            size_t off = (size_t)(row0 + r) * 128 + q0 + c4;
            *reinterpret_cast<float4*>(&out[off]) = v;
            if (dup) *reinterpret_cast<float4*>(&out[ndup + off]) = v;
        }
    }
}

// ---------------------------------------------------------------------------
extern "C" void kernel_launch(void* const* d_in, const int* in_sizes, int n_in,
                              void* d_out, int out_size) {
    const float* hidden = (const float*)d_in[0];
    const int*   src    = (const int*)d_in[1];
    const int*   dst    = (const int*)d_in[2];
    const float* W_h    = (const float*)d_in[3];
    const float* W_hf   = (const float*)d_in[4];
    float* out = (float*)d_out;

    int n = in_sizes[0] / 128;
    int e = in_sizes[1];
    int nb = (n + CHUNK - 1) / CHUNK;
    int dup = (out_size >= 2 * n * 128) ? 1 : 0;
    const int SMEM_G1 = 2 * 34816;                 // 69632
    const int SMEM_G2 = 34816 + 2 * (128 * 144);   // 71680

    // Lazy one-time resources (created on the non-captured correctness call).
    static cudaStream_t side = nullptr;
    static cudaEvent_t ev_fork = nullptr, ev_zero = nullptr, ev_join = nullptr,
                       ev_end = nullptr;
    static cudaEvent_t ev_g[NCHUNK] = {nullptr, nullptr, nullptr, nullptr};
    if (side == nullptr) {
        cudaStreamCreateWithFlags(&side, cudaStreamNonBlocking);
        cudaEventCreateWithFlags(&ev_fork, cudaEventDisableTiming);
        cudaEventCreateWithFlags(&ev_zero, cudaEventDisableTiming);
        cudaEventCreateWithFlags(&ev_join, cudaEventDisableTiming);
        cudaEventCreateWithFlags(&ev_end, cudaEventDisableTiming);
        for (int c = 0; c < NCHUNK; c++)
            cudaEventCreateWithFlags(&ev_g[c], cudaEventDisableTiming);
        cudaFuncSetAttribute(gemm1_mma, cudaFuncAttributeMaxDynamicSharedMemorySize, SMEM_G1);
        cudaFuncSetAttribute(gemm2_mma, cudaFuncAttributeMaxDynamicSharedMemorySize, SMEM_G2);
    }

    // ---- fork ----
    cudaEventRecord(ev_fork, 0);
    cudaStreamWaitEvent(side, ev_fork, 0);
    wht_prep_kernel<<<128, 256, 0, side>>>(W_h);

    // main: zero degrees (both arrays), record for side's outdeg
    zero_deg_kernel<<<(n + 255) / 256, 256>>>(n);
    cudaEventRecord(ev_zero, 0);

    // side: outdeg -> gemm1 (emits H23h + hsc)
    cudaStreamWaitEvent(side, ev_zero, 0);
    outdeg_kernel<<<(e / 4 + 255) / 256, 256, 0, side>>>(src, e);
    gemm1_mma<<<dim3(2, (n + 127) / 128), 256, SMEM_G1, side>>>(hidden, n);
    cudaEventRecord(ev_join, side);

    // main: indeg -> CSR build; wc for gemm2's B
    indeg_kernel<<<(e / 4 + 255) / 256, 256>>>(dst, e);
    wc_kernel<<<128, 256>>>(W_h, W_hf);
    chunk_reduce_kernel<<<nb, 256>>>(n);
    chunk_scan_kernel<<<nb, 256>>>(n, nb);
    fill_kernel<<<(e / 4 + 255) / 256, 256>>>(src, dst, e);

    // ---- join, then pipelined gather (stream 0) / gemm2 (side) over chunks ----
    cudaStreamWaitEvent(0, ev_join, 0);

    int nblk = (n + 127) / 128;
    int blk_per_chunk = (nblk + NCHUNK - 1) / NCHUNK;
    for (int c = 0; c < NCHUNK; c++) {
        int b0 = c * blk_per_chunk;
        if (b0 >= nblk) break;
        int bcnt = min(blk_per_chunk, nblk - b0);
        int node0 = b0 * 128;
        int node1 = min(node0 + bcnt * 128, n);
        int warps = node1 - node0;
        gather_kernel<<<(warps * 32 + 255) / 256, 256>>>(node0, node1);
        cudaEventRecord(ev_g[c], 0);
        cudaStreamWaitEvent(side, ev_g[c], 0);
        gemm2_mma<<<dim3(2, bcnt), 256, SMEM_G2, side>>>(out, n, dup, node0);
    }
    cudaEventRecord(ev_end, side);
    cudaStreamWaitEvent(0, ev_end, 0);
}

// round 15
// speedup vs baseline: 1.1207x; 1.1207x over previous
#include <cuda_runtime.h>
#include <cuda_fp16.h>
#include <cuda_bf16.h>

#define MAXN 100000
#define MAXE 3200000
#define CHUNK 2048
#define MAXNB ((MAXN + CHUNK - 1) / CHUNK)

// Scratch (device globals; allocation is forbidden)
__device__ __half g_hsc[MAXN * 128];   // fp16(hidden * rsqrt(outdeg))
__device__ __half g_aggh[MAXN * 128];  // fp16(rsin * sum hsc[src])
__device__ __half g_H23h[MAXN * 256];  // fp16(hidden @ W_h[:,128:384]) -> [h2 | h3]
__device__ __half g_WhT[256 * 128];    // fp16(W_h[:,128:384])^T : [c][k]
__device__ __half g_WcT[256 * 128];    // fp16(Wc)^T phys-interleaved : [2c+q][k]
__device__ int    g_outdeg[MAXN];
__device__ int    g_indeg[MAXN];
__device__ int    g_rowptr[MAXN + 1];
__device__ int    g_cursor[MAXN];
__device__ int    g_csr[MAXE];
__device__ int    g_bsum[MAXNB];

typedef unsigned int uint;

__device__ __forceinline__ void mma16816(float4& c, uint a0, uint a1, uint a2, uint a3,
                                         uint b0, uint b1) {
    asm volatile(
        "mma.sync.aligned.m16n8k16.row.col.f32.f16.f16.f32 "
        "{%0,%1,%2,%3}, {%4,%5,%6,%7}, {%8,%9}, {%0,%1,%2,%3};"
        : "+f"(c.x), "+f"(c.y), "+f"(c.z), "+f"(c.w)
        : "r"(a0), "r"(a1), "r"(a2), "r"(a3), "r"(b0), "r"(b1));
}

// ---------------------------------------------------------------------------
// WhT[c][k] = fp16(W_h[k][128+c])
__global__ void wht_prep_kernel(const float* __restrict__ W_h) {
    int k = blockIdx.x;     // 0..127
    int c = threadIdx.x;    // 0..255
    g_WhT[(size_t)c * 128 + k] = __float2half(W_h[(size_t)k * 384 + 128 + c]);
}

// WcT[phys][k] = fp16( (W_h[:,0:128] @ W_hf)[k][j] ), phys interleaves f1/f2
__global__ __launch_bounds__(256) void wc_kernel(const float* __restrict__ W_h,
                                                 const float* __restrict__ W_hf) {
    __shared__ float row[128];
    int k = blockIdx.x;
    int j = threadIdx.x;
    if (j < 128) row[j] = W_h[(size_t)k * 384 + j];
    __syncthreads();
    float acc = 0.f;
#pragma unroll 8
    for (int m = 0; m < 128; m++) acc = fmaf(row[m], W_hf[(size_t)m * 256 + j], acc);
    int phys = (j < 128) ? (2 * j) : (2 * (j - 128) + 1);
    g_WcT[(size_t)phys * 128 + k] = __float2half(acc);
}

__global__ void outdeg_kernel(const int* __restrict__ src, int e) {
    int i = blockIdx.x * blockDim.x + threadIdx.x;
    int i4 = i * 4;
    if (i4 + 3 < e) {
        int4 s = *reinterpret_cast<const int4*>(&src[i4]);
        atomicAdd(&g_outdeg[s.x], 1); atomicAdd(&g_outdeg[s.y], 1);
        atomicAdd(&g_outdeg[s.z], 1); atomicAdd(&g_outdeg[s.w], 1);
    } else {
        for (int j = i4; j < e; j++) atomicAdd(&g_outdeg[src[j]], 1);
    }
}

__global__ void indeg_kernel(const int* __restrict__ dst, int e) {
    int i = blockIdx.x * blockDim.x + threadIdx.x;
    int i4 = i * 4;
    if (i4 + 3 < e) {
        int4 d = *reinterpret_cast<const int4*>(&dst[i4]);
        atomicAdd(&g_indeg[d.x], 1); atomicAdd(&g_indeg[d.y], 1);
        atomicAdd(&g_indeg[d.z], 1); atomicAdd(&g_indeg[d.w], 1);
    } else {
        for (int j = i4; j < e; j++) atomicAdd(&g_indeg[dst[j]], 1);
    }
}

// --------------------------- scan (2 kernels) ------------------------------
__global__ __launch_bounds__(256) void chunk_reduce_kernel(int n) {
    __shared__ int wsum[8];
    int b = blockIdx.x;
    int base = b * CHUNK;
    int tid = threadIdx.x, lane = tid & 31, wid = tid >> 5;
    int s = 0;
#pragma unroll
    for (int j = 0; j < CHUNK / 256; j++) {
        int idx = base + tid + j * 256;
        s += (idx < n) ? g_indeg[idx] : 0;
    }
#pragma unroll
    for (int o = 16; o > 0; o >>= 1) s += __shfl_down_sync(0xFFFFFFFFu, s, o);
    if (lane == 0) wsum[wid] = s;
    __syncthreads();
    if (tid == 0) {
        int t = 0;
#pragma unroll
        for (int w = 0; w < 8; w++) t += wsum[w];
        g_bsum[b] = t;
    }
}

// chunk_scan computes its own block offset from g_bsum (nb <= 64)
__global__ __launch_bounds__(256) void chunk_scan_kernel(int n, int nb) {
    __shared__ int wsum[8];
    __shared__ int part[2];
    __shared__ int chunk_total;
    int b = blockIdx.x;
    int base = b * CHUNK;
    int tid = threadIdx.x, lane = tid & 31, wid = tid >> 5;

    if (tid < 64) {
        int v = (tid < b) ? g_bsum[tid] : 0;
#pragma unroll
        for (int o = 16; o > 0; o >>= 1) v += __shfl_down_sync(0xFFFFFFFFu, v, o);
        if ((tid & 31) == 0) part[tid >> 5] = v;
    }

    int vals[8];
    int s = 0;
#pragma unroll
    for (int j = 0; j < 8; j++) {
        int idx = base + tid * 8 + j;
        vals[j] = (idx < n) ? g_indeg[idx] : 0;
        s += vals[j];
    }
    int x = s;
#pragma unroll
    for (int o = 1; o < 32; o <<= 1) {
        int y = __shfl_up_sync(0xFFFFFFFFu, x, o);
        if (lane >= o) x += y;
    }
    if (lane == 31) wsum[wid] = x;
    __syncthreads();
    if (tid == 0) {
        int acc = 0;
#pragma unroll
        for (int w = 0; w < 8; w++) { int v = wsum[w]; wsum[w] = acc; acc += v; }
        chunk_total = acc;
    }
    __syncthreads();
    int boff = part[0] + part[1];
    int prefix = boff + wsum[wid] + (x - s);
#pragma unroll
    for (int j = 0; j < 8; j++) {
        int idx = base + tid * 8 + j;
        if (idx < n) { g_rowptr[idx] = prefix; g_cursor[idx] = prefix; }
        prefix += vals[j];
    }
    if (tid == 0 && b == nb - 1) g_rowptr[n] = boff + chunk_total;
}

__global__ void fill_kernel(const int* __restrict__ src, const int* __restrict__ dst, int e) {
    int i = blockIdx.x * blockDim.x + threadIdx.x;
    int i4 = i * 4;
    if (i4 + 3 < e) {
        int4 s = *reinterpret_cast<const int4*>(&src[i4]);
        int4 d = *reinterpret_cast<const int4*>(&dst[i4]);
        g_csr[atomicAdd(&g_cursor[d.x], 1)] = s.x;
        g_csr[atomicAdd(&g_cursor[d.y], 1)] = s.y;
        g_csr[atomicAdd(&g_cursor[d.z], 1)] = s.z;
        g_csr[atomicAdd(&g_cursor[d.w], 1)] = s.w;
    } else {
        for (int j = i4; j < e; j++)
            g_csr[atomicAdd(&g_cursor[dst[j]], 1)] = src[j];
    }
}

// ---------------------------------------------------------------------------
// Gather: one warp per dst node. aggh[d] = fp16(rsin[d] * sum_e hsc[src_e])
__global__ __launch_bounds__(256) void gather_kernel(int n) {
    int node = (blockIdx.x * blockDim.x + threadIdx.x) >> 5;
    int lane = threadIdx.x & 31;
    if (node >= n) return;
    int beg = g_rowptr[node];
    int end = g_rowptr[node + 1];

    float4 acc0 = make_float4(0.f, 0.f, 0.f, 0.f);
    float4 acc1 = make_float4(0.f, 0.f, 0.f, 0.f);
    int e = beg;
    for (; e + 3 < end; e += 4) {
        int s0 = g_csr[e], s1 = g_csr[e + 1], s2 = g_csr[e + 2], s3 = g_csr[e + 3];
        uint2 v0 = *reinterpret_cast<const uint2*>(&g_hsc[(size_t)s0 * 128 + lane * 4]);
        uint2 v1 = *reinterpret_cast<const uint2*>(&g_hsc[(size_t)s1 * 128 + lane * 4]);
        uint2 v2 = *reinterpret_cast<const uint2*>(&g_hsc[(size_t)s2 * 128 + lane * 4]);
        uint2 v3 = *reinterpret_cast<const uint2*>(&g_hsc[(size_t)s3 * 128 + lane * 4]);
        float2 a0 = __half22float2(*reinterpret_cast<__half2*>(&v0.x));
        float2 a1 = __half22float2(*reinterpret_cast<__half2*>(&v0.y));
        float2 b0 = __half22float2(*reinterpret_cast<__half2*>(&v1.x));
        float2 b1 = __half22float2(*reinterpret_cast<__half2*>(&v1.y));
        float2 c0 = __half22float2(*reinterpret_cast<__half2*>(&v2.x));
        float2 c1 = __half22float2(*reinterpret_cast<__half2*>(&v2.y));
        float2 d0 = __half22float2(*reinterpret_cast<__half2*>(&v3.x));
        float2 d1 = __half22float2(*reinterpret_cast<__half2*>(&v3.y));
        acc0.x += a0.x + b0.x; acc0.y += a0.y + b0.y;
        acc0.z += a1.x + b1.x; acc0.w += a1.y + b1.y;
        acc1.x += c0.x + d0.x; acc1.y += c0.y + d0.y;
        acc1.z += c1.x + d1.x; acc1.w += c1.y + d1.y;
    }
    for (; e < end; e++) {
        int s0 = g_csr[e];
        uint2 v0 = *reinterpret_cast<const uint2*>(&g_hsc[(size_t)s0 * 128 + lane * 4]);
        float2 a0 = __half22float2(*reinterpret_cast<__half2*>(&v0.x));
        float2 a1 = __half22float2(*reinterpret_cast<__half2*>(&v0.y));
        acc0.x += a0.x; acc0.y += a0.y; acc0.z += a1.x; acc0.w += a1.y;
    }
    float ri = rsqrtf((float)max(end - beg, 1));
    __half2 p0 = __floats2half2_rn((acc0.x + acc1.x) * ri, (acc0.y + acc1.y) * ri);
    __half2 p1 = __floats2half2_rn((acc0.z + acc1.z) * ri, (acc0.w + acc1.w) * ri);
    uint2 st;
    st.x = *reinterpret_cast<uint*>(&p0);
    st.y = *reinterpret_cast<uint*>(&p1);
    *reinterpret_cast<uint2*>(&g_aggh[(size_t)node * 128 + lane * 4]) = st;
}

// ---------------------------------------------------------------------------
// GEMM1 (tensor core): H23h[n,256] = fp16( hidden[n,128] @ W_h[:,128:384] )
// BM=128, BN=128, K=128 in smem. col0==0 blocks also emit hsc during A-fill.
__global__ __launch_bounds__(256) void gemm1_mma(const float* __restrict__ hidden, int n) {
    extern __shared__ char smem[];
    __half (*As)[136] = reinterpret_cast<__half(*)[136]>(smem);
    __half (*Bs)[136] = reinterpret_cast<__half(*)[136]>(smem + 34816);
    __half (*Os)[136] = reinterpret_cast<__half(*)[136]>(smem);  // reuse As post-mma

    int tid = threadIdx.x;
    int row0 = blockIdx.y * 128;
    int col0 = blockIdx.x * 128;

    // A fill (fp32 -> fp16); col0==0 blocks also write hsc = fp16(h * rsout)
#pragma unroll
    for (int i = 0; i < 8; i++) {
        int lin = tid + i * 256;  // 2048 slots of 8 halves
        int r = lin >> 4;
        int kc = (lin & 15) * 8;
        int grow = row0 + r;
        float4 a = make_float4(0.f, 0.f, 0.f, 0.f), b = a;
        if (grow < n) {
            const float4* p = reinterpret_cast<const float4*>(&hidden[(size_t)grow * 128 + kc]);
            a = p[0]; b = p[1];
        }
        __half2 h0 = __floats2half2_rn(a.x, a.y);
        __half2 h1 = __floats2half2_rn(a.z, a.w);
        __half2 h2 = __floats2half2_rn(b.x, b.y);
        __half2 h3 = __floats2half2_rn(b.z, b.w);
        uint4 o;
        o.x = *reinterpret_cast<uint*>(&h0); o.y = *reinterpret_cast<uint*>(&h1);
        o.z = *reinterpret_cast<uint*>(&h2); o.w = *reinterpret_cast<uint*>(&h3);
        *reinterpret_cast<uint4*>(&As[r][kc]) = o;

        if (col0 == 0 && grow < n) {
            float rs = rsqrtf((float)max(g_outdeg[grow], 1));
            __half2 s0 = __floats2half2_rn(a.x * rs, a.y * rs);
            __half2 s1 = __floats2half2_rn(a.z * rs, a.w * rs);
            __half2 s2 = __floats2half2_rn(b.x * rs, b.y * rs);
            __half2 s3 = __floats2half2_rn(b.z * rs, b.w * rs);
            uint4 os;
            os.x = *reinterpret_cast<uint*>(&s0); os.y = *reinterpret_cast<uint*>(&s1);
            os.z = *reinterpret_cast<uint*>(&s2); os.w = *reinterpret_cast<uint*>(&s3);
            *reinterpret_cast<uint4*>(&g_hsc[(size_t)grow * 128 + kc]) = os;
        }
    }
    // B fill (coalesced from transposed fp16 weights)
#pragma unroll
    for (int i = 0; i < 8; i++) {
        int lin = tid + i * 256;
        int r = lin >> 4;
        int kc = (lin & 15) * 8;
        *reinterpret_cast<uint4*>(&Bs[r][kc]) =
            *reinterpret_cast<const uint4*>(&g_WhT[(size_t)(col0 + r) * 128 + kc]);
    }
    __syncthreads();

    int w = tid >> 5, lane = tid & 31;
    int g = lane >> 2, tig = lane & 3;
    int m0 = (w >> 1) * 32;
    int n0 = (w & 1) * 64;

    float4 acc[2][8];
#pragma unroll
    for (int mt = 0; mt < 2; mt++)
#pragma unroll
        for (int j = 0; j < 8; j++) acc[mt][j] = make_float4(0.f, 0.f, 0.f, 0.f);

#pragma unroll
    for (int kt = 0; kt < 128; kt += 16) {
        uint a[2][4];
#pragma unroll
        for (int mt = 0; mt < 2; mt++) {
            int mr = m0 + mt * 16 + g;
            a[mt][0] = *reinterpret_cast<const uint*>(&As[mr][kt + tig * 2]);
            a[mt][1] = *reinterpret_cast<const uint*>(&As[mr + 8][kt + tig * 2]);
            a[mt][2] = *reinterpret_cast<const uint*>(&As[mr][kt + tig * 2 + 8]);
            a[mt][3] = *reinterpret_cast<const uint*>(&As[mr + 8][kt + tig * 2 + 8]);
        }
#pragma unroll
        for (int j = 0; j < 8; j++) {
            int nc = n0 + j * 8 + g;
            uint b0 = *reinterpret_cast<const uint*>(&Bs[nc][kt + tig * 2]);
            uint b1 = *reinterpret_cast<const uint*>(&Bs[nc][kt + tig * 2 + 8]);
            mma16816(acc[0][j], a[0][0], a[0][1], a[0][2], a[0][3], b0, b1);
            mma16816(acc[1][j], a[1][0], a[1][1], a[1][2], a[1][3], b0, b1);
        }
    }
    __syncthreads();

    // Stage results in smem, then coalesced store
#pragma unroll
    for (int mt = 0; mt < 2; mt++) {
#pragma unroll
        for (int j = 0; j < 8; j++) {
            int r1 = m0 + mt * 16 + g;
            int c = n0 + j * 8 + tig * 2;
            __half2 lo = __floats2half2_rn(acc[mt][j].x, acc[mt][j].y);
            __half2 hi = __floats2half2_rn(acc[mt][j].z, acc[mt][j].w);
            *reinterpret_cast<uint*>(&Os[r1][c]) = *reinterpret_cast<uint*>(&lo);
            *reinterpret_cast<uint*>(&Os[r1 + 8][c]) = *reinterpret_cast<uint*>(&hi);
        }
    }
    __syncthreads();
#pragma unroll
    for (int i = 0; i < 8; i++) {
        int lin = tid + i * 256;
        int r = lin >> 4;
        int kc = (lin & 15) * 8;
        if (row0 + r < n)
            *reinterpret_cast<uint4*>(&g_H23h[(size_t)(row0 + r) * 256 + col0 + kc]) =
                *reinterpret_cast<const uint4*>(&Os[r][kc]);
    }
}

// ---------------------------------------------------------------------------
// GEMM2 (tensor core) fused with gated epilogue; smem-staged I/O.
// H2s/H3s rows padded to 72 halves (144B = 9*16B) so uint4 accesses stay aligned.
__global__ __launch_bounds__(256) void gemm2_mma(float* __restrict__ out, int n, int dup) {
    extern __shared__ char smem[];
    __half (*As)[136] = reinterpret_cast<__half(*)[136]>(smem);
    __half (*Bs)[136] = reinterpret_cast<__half(*)[136]>(smem + 34816);
    __half (*H2s)[72] = reinterpret_cast<__half(*)[72]>(smem + 34816);            // reuse Bs
    __half (*H3s)[72] = reinterpret_cast<__half(*)[72]>(smem + 34816 + 18432);
    float (*Os)[68]   = reinterpret_cast<float(*)[68]>(smem);                     // reuse As

    int tid = threadIdx.x;
    int row0 = blockIdx.y * 128;
    int col0 = blockIdx.x * 128;  // phys col in [0,256)
    int q0 = col0 >> 1;           // logical col base (0 or 64)

#pragma unroll
    for (int i = 0; i < 8; i++) {
        int lin = tid + i * 256;
        int r = lin >> 4;
        int kc = (lin & 15) * 8;
        uint4 v = make_uint4(0, 0, 0, 0);
        if (row0 + r < n)
            v = *reinterpret_cast<const uint4*>(&g_aggh[(size_t)(row0 + r) * 128 + kc]);
        *reinterpret_cast<uint4*>(&As[r][kc]) = v;
    }
#pragma unroll
    for (int i = 0; i < 8; i++) {
        int lin = tid + i * 256;
        int r = lin >> 4;
        int kc = (lin & 15) * 8;
        *reinterpret_cast<uint4*>(&Bs[r][kc]) =
            *reinterpret_cast<const uint4*>(&g_WcT[(size_t)(col0 + r) * 128 + kc]);
    }
    __syncthreads();

    int w = tid >> 5, lane = tid & 31;
    int g = lane >> 2, tig = lane & 3;
    int m0 = (w >> 1) * 32;
    int n0 = (w & 1) * 64;

    float4 acc[2][8];
#pragma unroll
    for (int mt = 0; mt < 2; mt++)
#pragma unroll
        for (int j = 0; j < 8; j++) acc[mt][j] = make_float4(0.f, 0.f, 0.f, 0.f);

#pragma unroll
    for (int kt = 0; kt < 128; kt += 16) {
        uint a[2][4];
#pragma unroll
        for (int mt = 0; mt < 2; mt++) {
            int mr = m0 + mt * 16 + g;
            a[mt][0] = *reinterpret_cast<const uint*>(&As[mr][kt + tig * 2]);
            a[mt][1] = *reinterpret_cast<const uint*>(&As[mr + 8][kt + tig * 2]);
            a[mt][2] = *reinterpret_cast<const uint*>(&As[mr][kt + tig * 2 + 8]);
            a[mt][3] = *reinterpret_cast<const uint*>(&As[mr + 8][kt + tig * 2 + 8]);
        }
#pragma unroll
        for (int j = 0; j < 8; j++) {
            int nc = n0 + j * 8 + g;
            uint b0 = *reinterpret_cast<const uint*>(&Bs[nc][kt + tig * 2]);
            uint b1 = *reinterpret_cast<const uint*>(&Bs[nc][kt + tig * 2 + 8]);
            mma16816(acc[0][j], a[0][0], a[0][1], a[0][2], a[0][3], b0, b1);
            mma16816(acc[1][j], a[1][0], a[1][1], a[1][2], a[1][3], b0, b1);
        }
    }
    __syncthreads();

    // Load H23 tile (coalesced) into smem: h2/h3 logical cols [q0, q0+64)
#pragma unroll
    for (int i = 0; i < 8; i++) {
        int lin = tid + i * 256;   // 2048 slots of 8 halves
        int a = lin >> 10;         // 0 = h2, 1 = h3
        int rem = lin & 1023;
        int r = rem >> 3;
        int c8 = (rem & 7) * 8;
        uint4 v = make_uint4(0, 0, 0, 0);
        if (row0 + r < n)
            v = *reinterpret_cast<const uint4*>(
                &g_H23h[(size_t)(row0 + r) * 256 + a * 128 + q0 + c8]);
        if (a == 0) *reinterpret_cast<uint4*>(&H2s[r][c8]) = v;
        else        *reinterpret_cast<uint4*>(&H3s[r][c8]) = v;
    }
    __syncthreads();

    // Epilogue into smem: phys pair (acc.x=f1, acc.y=f2) -> logical qloc
#pragma unroll
    for (int mt = 0; mt < 2; mt++) {
#pragma unroll
        for (int j = 0; j < 8; j++) {
            int r1 = m0 + mt * 16 + g;
            int r2 = r1 + 8;
            int qloc = (n0 >> 1) + j * 4 + tig;
            float h2a = __half2float(H2s[r1][qloc]);
            float h3a = __half2float(H3s[r1][qloc]);
            Os[r1][qloc] = h3a + fmaxf(acc[mt][j].x + h2a, 0.f) * acc[mt][j].y;
            float h2b = __half2float(H2s[r2][qloc]);
            float h3b = __half2float(H3s[r2][qloc]);
            Os[r2][qloc] = h3b + fmaxf(acc[mt][j].z + h2b, 0.f) * acc[mt][j].w;
        }
    }
    __syncthreads();

    // Coalesced store of 128 x 64 fp32 tile (+ duplicate half)
    size_t ndup = (size_t)n * 128;
#pragma unroll
    for (int i = 0; i < 8; i++) {
        int lin = tid + i * 256;   // 2048 float4 slots
        int r = lin >> 4;
        int c4 = (lin & 15) * 4;
        if (row0 + r < n) {
            float4 v = *reinterpret_cast<const float4*>(&Os[r][c4]);
            size_t off = (size_t)(row0 + r) * 128 + q0 + c4;
            *reinterpret_cast<float4*>(&out[off]) = v;
            if (dup) *reinterpret_cast<float4*>(&out[ndup + off]) = v;
        }
    }
}

// ---------------------------------------------------------------------------
extern "C" void kernel_launch(void* const* d_in, const int* in_sizes, int n_in,
                              void* d_out, int out_size) {
    const float* hidden = (const float*)d_in[0];
    const int*   src    = (const int*)d_in[1];
    const int*   dst    = (const int*)d_in[2];
    const float* W_h    = (const float*)d_in[3];
    const float* W_hf   = (const float*)d_in[4];
    float* out = (float*)d_out;

    int n = in_sizes[0] / 128;
    int e = in_sizes[1];
    int nb = (n + CHUNK - 1) / CHUNK;
    int dup = (out_size >= 2 * n * 128) ? 1 : 0;
    const int SMEM_G1 = 2 * 34816;                 // 69632
    const int SMEM_G2 = 34816 + 2 * (128 * 144);   // 71680

    // Lazy one-time resources (created on the non-captured correctness call).
    static cudaStream_t side = nullptr;
    static cudaEvent_t ev_fork = nullptr, ev_zero = nullptr, ev_join = nullptr;
    static int* p_outdeg = nullptr;
    static int* p_indeg = nullptr;
    if (side == nullptr) {
        cudaStreamCreateWithFlags(&side, cudaStreamNonBlocking);
        cudaEventCreateWithFlags(&ev_fork, cudaEventDisableTiming);
        cudaEventCreateWithFlags(&ev_zero, cudaEventDisableTiming);
        cudaEventCreateWithFlags(&ev_join, cudaEventDisableTiming);
        cudaGetSymbolAddress((void**)&p_outdeg, g_outdeg);
        cudaGetSymbolAddress((void**)&p_indeg, g_indeg);
        cudaFuncSetAttribute(gemm1_mma, cudaFuncAttributeMaxDynamicSharedMemorySize, SMEM_G1);
        cudaFuncSetAttribute(gemm2_mma, cudaFuncAttributeMaxDynamicSharedMemorySize, SMEM_G2);
    }

    // ---- fork ----
    cudaEventRecord(ev_fork, 0);
    cudaStreamWaitEvent(side, ev_fork, 0);
    wht_prep_kernel<<<128, 256, 0, side>>>(W_h);

    // main: zero degree arrays via memset (capturable), record for side's outdeg
    cudaMemsetAsync(p_outdeg, 0, (size_t)n * sizeof(int), 0);
    cudaMemsetAsync(p_indeg, 0, (size_t)n * sizeof(int), 0);
    cudaEventRecord(ev_zero, 0);

    // side: outdeg -> gemm1 (emits H23h + hsc)
    cudaStreamWaitEvent(side, ev_zero, 0);
    outdeg_kernel<<<(e / 4 + 255) / 256, 256, 0, side>>>(src, e);
    gemm1_mma<<<dim3(2, (n + 127) / 128), 256, SMEM_G1, side>>>(hidden, n);
    cudaEventRecord(ev_join, side);

    // main: indeg -> CSR build; wc for gemm2's B
    indeg_kernel<<<(e / 4 + 255) / 256, 256>>>(dst, e);
    wc_kernel<<<128, 256>>>(W_h, W_hf);
    chunk_reduce_kernel<<<nb, 256>>>(n);
    chunk_scan_kernel<<<nb, 256>>>(n, nb);
    fill_kernel<<<(e / 4 + 255) / 256, 256>>>(src, dst, e);

    // ---- join: gather needs hsc (gemm1) + csr ----
    cudaStreamWaitEvent(0, ev_join, 0);
    gather_kernel<<<(n * 32 + 255) / 256, 256>>>(n);
    gemm2_mma<<<dim3(2, (n + 127) / 128), 256, SMEM_G2>>>(out, n, dup);
}

// round 16
// speedup vs baseline: 1.1582x; 1.0335x over previous
#include <cuda_runtime.h>
#include <cuda_fp16.h>
#include <cuda_bf16.h>

#define MAXN 100000
#define MAXE 3200000
#define CHUNK 2048
#define MAXNB ((MAXN + CHUNK - 1) / CHUNK)

// Scratch (device globals; allocation is forbidden)
__device__ __half g_hsc[MAXN * 128];   // fp16(hidden * rsqrt(outdeg))
__device__ __half g_aggh[MAXN * 128];  // fp16(rsin * sum hsc[src])
__device__ __half g_H23h[MAXN * 256];  // fp16(hidden @ W_h[:,128:384]) -> [h2 | h3]
__device__ __half g_WhT[256 * 128];    // fp16(W_h[:,128:384])^T : [c][k]
__device__ __half g_WcT[256 * 128];    // fp16(Wc)^T phys-interleaved : [2c+q][k]
__device__ int    g_outdeg[MAXN];
__device__ int    g_indeg[MAXN];
__device__ int    g_rowptr[MAXN + 1];
__device__ int    g_cursor[MAXN];
__device__ int    g_csr[MAXE];
__device__ int    g_bsum[MAXNB];

typedef unsigned int uint;

__device__ __forceinline__ void mma16816(float4& c, uint a0, uint a1, uint a2, uint a3,
                                         uint b0, uint b1) {
    asm volatile(
        "mma.sync.aligned.m16n8k16.row.col.f32.f16.f16.f32 "
        "{%0,%1,%2,%3}, {%4,%5,%6,%7}, {%8,%9}, {%0,%1,%2,%3};"
        : "+f"(c.x), "+f"(c.y), "+f"(c.z), "+f"(c.w)
        : "r"(a0), "r"(a1), "r"(a2), "r"(a3), "r"(b0), "r"(b1));
}

// ---------------------------------------------------------------------------
// Combined weight prep: WhT[c][k] = fp16(W_h[k][128+c]) and
// WcT[phys][k] = fp16( (W_h[:,0:128] @ W_hf)[k][j] ), phys interleaves f1/f2.
__global__ __launch_bounds__(256) void wprep_kernel(const float* __restrict__ W_h,
                                                    const float* __restrict__ W_hf) {
    __shared__ float row[128];
    int k = blockIdx.x;   // 0..127
    int j = threadIdx.x;  // 0..255

    // WhT
    g_WhT[(size_t)j * 128 + k] = __float2half(W_h[(size_t)k * 384 + 128 + j]);

    // Wc row
    if (j < 128) row[j] = W_h[(size_t)k * 384 + j];
    __syncthreads();
    float acc = 0.f;
#pragma unroll 8
    for (int m = 0; m < 128; m++) acc = fmaf(row[m], W_hf[(size_t)m * 256 + j], acc);
    int phys = (j < 128) ? (2 * j) : (2 * (j - 128) + 1);
    g_WcT[(size_t)phys * 128 + k] = __float2half(acc);
}

__global__ void outdeg_kernel(const int* __restrict__ src, int e) {
    int i = blockIdx.x * blockDim.x + threadIdx.x;
    int i4 = i * 4;
    if (i4 + 3 < e) {
        int4 s = *reinterpret_cast<const int4*>(&src[i4]);
        atomicAdd(&g_outdeg[s.x], 1); atomicAdd(&g_outdeg[s.y], 1);
        atomicAdd(&g_outdeg[s.z], 1); atomicAdd(&g_outdeg[s.w], 1);
    } else {
        for (int j = i4; j < e; j++) atomicAdd(&g_outdeg[src[j]], 1);
    }
}

__global__ void indeg_kernel(const int* __restrict__ dst, int e) {
    int i = blockIdx.x * blockDim.x + threadIdx.x;
    int i4 = i * 4;
    if (i4 + 3 < e) {
        int4 d = *reinterpret_cast<const int4*>(&dst[i4]);
        atomicAdd(&g_indeg[d.x], 1); atomicAdd(&g_indeg[d.y], 1);
        atomicAdd(&g_indeg[d.z], 1); atomicAdd(&g_indeg[d.w], 1);
    } else {
        for (int j = i4; j < e; j++) atomicAdd(&g_indeg[dst[j]], 1);
    }
}

// --------------------------- scan (2 kernels) ------------------------------
__global__ __launch_bounds__(256) void chunk_reduce_kernel(int n) {
    __shared__ int wsum[8];
    int b = blockIdx.x;
    int base = b * CHUNK;
    int tid = threadIdx.x, lane = tid & 31, wid = tid >> 5;
    int s = 0;
#pragma unroll
    for (int j = 0; j < CHUNK / 256; j++) {
        int idx = base + tid + j * 256;
        s += (idx < n) ? g_indeg[idx] : 0;
    }
#pragma unroll
    for (int o = 16; o > 0; o >>= 1) s += __shfl_down_sync(0xFFFFFFFFu, s, o);
    if (lane == 0) wsum[wid] = s;
    __syncthreads();
    if (tid == 0) {
        int t = 0;
#pragma unroll
        for (int w = 0; w < 8; w++) t += wsum[w];
        g_bsum[b] = t;
    }
}

// chunk_scan computes its own block offset from g_bsum (nb <= 64)
__global__ __launch_bounds__(256) void chunk_scan_kernel(int n, int nb) {
    __shared__ int wsum[8];
    __shared__ int part[2];
    __shared__ int chunk_total;
    int b = blockIdx.x;
    int base = b * CHUNK;
    int tid = threadIdx.x, lane = tid & 31, wid = tid >> 5;

    if (tid < 64) {
        int v = (tid < b) ? g_bsum[tid] : 0;
#pragma unroll
        for (int o = 16; o > 0; o >>= 1) v += __shfl_down_sync(0xFFFFFFFFu, v, o);
        if ((tid & 31) == 0) part[tid >> 5] = v;
    }

    int vals[8];
    int s = 0;
#pragma unroll
    for (int j = 0; j < 8; j++) {
        int idx = base + tid * 8 + j;
        vals[j] = (idx < n) ? g_indeg[idx] : 0;
        s += vals[j];
    }
    int x = s;
#pragma unroll
    for (int o = 1; o < 32; o <<= 1) {
        int y = __shfl_up_sync(0xFFFFFFFFu, x, o);
        if (lane >= o) x += y;
    }
    if (lane == 31) wsum[wid] = x;
    __syncthreads();
    if (tid == 0) {
        int acc = 0;
#pragma unroll
        for (int w = 0; w < 8; w++) { int v = wsum[w]; wsum[w] = acc; acc += v; }
        chunk_total = acc;
    }
    __syncthreads();
    int boff = part[0] + part[1];
    int prefix = boff + wsum[wid] + (x - s);
#pragma unroll
    for (int j = 0; j < 8; j++) {
        int idx = base + tid * 8 + j;
        if (idx < n) { g_rowptr[idx] = prefix; g_cursor[idx] = prefix; }
        prefix += vals[j];
    }
    if (tid == 0 && b == nb - 1) g_rowptr[n] = boff + chunk_total;
}

__global__ void fill_kernel(const int* __restrict__ src, const int* __restrict__ dst, int e) {
    int i = blockIdx.x * blockDim.x + threadIdx.x;
    int i4 = i * 4;
    if (i4 + 3 < e) {
        int4 s = *reinterpret_cast<const int4*>(&src[i4]);
        int4 d = *reinterpret_cast<const int4*>(&dst[i4]);
        g_csr[atomicAdd(&g_cursor[d.x], 1)] = s.x;
        g_csr[atomicAdd(&g_cursor[d.y], 1)] = s.y;
        g_csr[atomicAdd(&g_cursor[d.z], 1)] = s.z;
        g_csr[atomicAdd(&g_cursor[d.w], 1)] = s.w;
    } else {
        for (int j = i4; j < e; j++)
            g_csr[atomicAdd(&g_cursor[dst[j]], 1)] = src[j];
    }
}

// ---------------------------------------------------------------------------
// Gather: one warp per dst node, half-warp per edge (lanes 0-15: even edges,
// lanes 16-31: odd edges), 16B uint4 loads. aggh[d] = fp16(rsin * sum hsc[src]).
__global__ __launch_bounds__(256) void gather_kernel(int n) {
    int node = (blockIdx.x * blockDim.x + threadIdx.x) >> 5;
    int lane = threadIdx.x & 31;
    if (node >= n) return;
    int half = lane >> 4;      // 0 or 1
    int hl = lane & 15;        // position within half-warp
    int beg = g_rowptr[node];
    int end = g_rowptr[node + 1];

    float a0 = 0.f, a1 = 0.f, a2 = 0.f, a3 = 0.f;
    float a4 = 0.f, a5 = 0.f, a6 = 0.f, a7 = 0.f;

    int e = beg + half;
    for (; e + 2 < end; e += 4) {
        int s0 = g_csr[e];
        int s1 = g_csr[e + 2];
        uint4 v0 = *reinterpret_cast<const uint4*>(&g_hsc[(size_t)s0 * 128 + hl * 8]);
        uint4 v1 = *reinterpret_cast<const uint4*>(&g_hsc[(size_t)s1 * 128 + hl * 8]);
        float2 p0 = __half22float2(*reinterpret_cast<__half2*>(&v0.x));
        float2 p1 = __half22float2(*reinterpret_cast<__half2*>(&v0.y));
        float2 p2 = __half22float2(*reinterpret_cast<__half2*>(&v0.z));
        float2 p3 = __half22float2(*reinterpret_cast<__half2*>(&v0.w));
        float2 q0 = __half22float2(*reinterpret_cast<__half2*>(&v1.x));
        float2 q1 = __half22float2(*reinterpret_cast<__half2*>(&v1.y));
        float2 q2 = __half22float2(*reinterpret_cast<__half2*>(&v1.z));
        float2 q3 = __half22float2(*reinterpret_cast<__half2*>(&v1.w));
        a0 += p0.x + q0.x; a1 += p0.y + q0.y;
        a2 += p1.x + q1.x; a3 += p1.y + q1.y;
        a4 += p2.x + q2.x; a5 += p2.y + q2.y;
        a6 += p3.x + q3.x; a7 += p3.y + q3.y;
    }
    if (e < end) {
        int s0 = g_csr[e];
        uint4 v0 = *reinterpret_cast<const uint4*>(&g_hsc[(size_t)s0 * 128 + hl * 8]);
        float2 p0 = __half22float2(*reinterpret_cast<__half2*>(&v0.x));
        float2 p1 = __half22float2(*reinterpret_cast<__half2*>(&v0.y));
        float2 p2 = __half22float2(*reinterpret_cast<__half2*>(&v0.z));
        float2 p3 = __half22float2(*reinterpret_cast<__half2*>(&v0.w));
        a0 += p0.x; a1 += p0.y; a2 += p1.x; a3 += p1.y;
        a4 += p2.x; a5 += p2.y; a6 += p3.x; a7 += p3.y;
    }

    // combine the two half-warps (lane i += lane i+16)
    a0 += __shfl_down_sync(0xFFFFFFFFu, a0, 16);
    a1 += __shfl_down_sync(0xFFFFFFFFu, a1, 16);
    a2 += __shfl_down_sync(0xFFFFFFFFu, a2, 16);
    a3 += __shfl_down_sync(0xFFFFFFFFu, a3, 16);
    a4 += __shfl_down_sync(0xFFFFFFFFu, a4, 16);
    a5 += __shfl_down_sync(0xFFFFFFFFu, a5, 16);
    a6 += __shfl_down_sync(0xFFFFFFFFu, a6, 16);
    a7 += __shfl_down_sync(0xFFFFFFFFu, a7, 16);

    if (half == 0) {
        float ri = rsqrtf((float)max(end - beg, 1));
        __half2 h0 = __floats2half2_rn(a0 * ri, a1 * ri);
        __half2 h1 = __floats2half2_rn(a2 * ri, a3 * ri);
        __half2 h2 = __floats2half2_rn(a4 * ri, a5 * ri);
        __half2 h3 = __floats2half2_rn(a6 * ri, a7 * ri);
        uint4 st;
        st.x = *reinterpret_cast<uint*>(&h0);
        st.y = *reinterpret_cast<uint*>(&h1);
        st.z = *reinterpret_cast<uint*>(&h2);
        st.w = *reinterpret_cast<uint*>(&h3);
        *reinterpret_cast<uint4*>(&g_aggh[(size_t)node * 128 + hl * 8]) = st;
    }
}

// ---------------------------------------------------------------------------
// GEMM1 (tensor core): H23h[n,256] = fp16( hidden[n,128] @ W_h[:,128:384] )
// BM=128, BN=128, K=128 in smem. col0==0 blocks also emit hsc during A-fill.
__global__ __launch_bounds__(256) void gemm1_mma(const float* __restrict__ hidden, int n) {
    extern __shared__ char smem[];
    __half (*As)[136] = reinterpret_cast<__half(*)[136]>(smem);
    __half (*Bs)[136] = reinterpret_cast<__half(*)[136]>(smem + 34816);
    __half (*Os)[136] = reinterpret_cast<__half(*)[136]>(smem);  // reuse As post-mma

    int tid = threadIdx.x;
    int row0 = blockIdx.y * 128;
    int col0 = blockIdx.x * 128;

    // A fill (fp32 -> fp16); col0==0 blocks also write hsc = fp16(h * rsout)
#pragma unroll
    for (int i = 0; i < 8; i++) {
        int lin = tid + i * 256;  // 2048 slots of 8 halves
        int r = lin >> 4;
        int kc = (lin & 15) * 8;
        int grow = row0 + r;
        float4 a = make_float4(0.f, 0.f, 0.f, 0.f), b = a;
        if (grow < n) {
            const float4* p = reinterpret_cast<const float4*>(&hidden[(size_t)grow * 128 + kc]);
            a = p[0]; b = p[1];
        }
        __half2 h0 = __floats2half2_rn(a.x, a.y);
        __half2 h1 = __floats2half2_rn(a.z, a.w);
        __half2 h2 = __floats2half2_rn(b.x, b.y);
        __half2 h3 = __floats2half2_rn(b.z, b.w);
        uint4 o;
        o.x = *reinterpret_cast<uint*>(&h0); o.y = *reinterpret_cast<uint*>(&h1);
        o.z = *reinterpret_cast<uint*>(&h2); o.w = *reinterpret_cast<uint*>(&h3);
        *reinterpret_cast<uint4*>(&As[r][kc]) = o;

        if (col0 == 0 && grow < n) {
            float rs = rsqrtf((float)max(g_outdeg[grow], 1));
            __half2 s0 = __floats2half2_rn(a.x * rs, a.y * rs);
            __half2 s1 = __floats2half2_rn(a.z * rs, a.w * rs);
            __half2 s2 = __floats2half2_rn(b.x * rs, b.y * rs);
            __half2 s3 = __floats2half2_rn(b.z * rs, b.w * rs);
            uint4 os;
            os.x = *reinterpret_cast<uint*>(&s0); os.y = *reinterpret_cast<uint*>(&s1);
            os.z = *reinterpret_cast<uint*>(&s2); os.w = *reinterpret_cast<uint*>(&s3);
            *reinterpret_cast<uint4*>(&g_hsc[(size_t)grow * 128 + kc]) = os;
        }
    }
    // B fill (coalesced from transposed fp16 weights)
#pragma unroll
    for (int i = 0; i < 8; i++) {
        int lin = tid + i * 256;
        int r = lin >> 4;
        int kc = (lin & 15) * 8;
        *reinterpret_cast<uint4*>(&Bs[r][kc]) =
            *reinterpret_cast<const uint4*>(&g_WhT[(size_t)(col0 + r) * 128 + kc]);
    }
    __syncthreads();

    int w = tid >> 5, lane = tid & 31;
    int g = lane >> 2, tig = lane & 3;
    int m0 = (w >> 1) * 32;
    int n0 = (w & 1) * 64;

    float4 acc[2][8];
#pragma unroll
    for (int mt = 0; mt < 2; mt++)
#pragma unroll
        for (int j = 0; j < 8; j++) acc[mt][j] = make_float4(0.f, 0.f, 0.f, 0.f);

#pragma unroll
    for (int kt = 0; kt < 128; kt += 16) {
        uint a[2][4];
#pragma unroll
        for (int mt = 0; mt < 2; mt++) {
            int mr = m0 + mt * 16 + g;
            a[mt][0] = *reinterpret_cast<const uint*>(&As[mr][kt + tig * 2]);
            a[mt][1] = *reinterpret_cast<const uint*>(&As[mr + 8][kt + tig * 2]);
            a[mt][2] = *reinterpret_cast<const uint*>(&As[mr][kt + tig * 2 + 8]);
            a[mt][3] = *reinterpret_cast<const uint*>(&As[mr + 8][kt + tig * 2 + 8]);
        }
#pragma unroll
        for (int j = 0; j < 8; j++) {
            int nc = n0 + j * 8 + g;
            uint b0 = *reinterpret_cast<const uint*>(&Bs[nc][kt + tig * 2]);
            uint b1 = *reinterpret_cast<const uint*>(&Bs[nc][kt + tig * 2 + 8]);
            mma16816(acc[0][j], a[0][0], a[0][1], a[0][2], a[0][3], b0, b1);
            mma16816(acc[1][j], a[1][0], a[1][1], a[1][2], a[1][3], b0, b1);
        }
    }
    __syncthreads();

    // Stage results in smem, then coalesced store
#pragma unroll
    for (int mt = 0; mt < 2; mt++) {
#pragma unroll
        for (int j = 0; j < 8; j++) {
            int r1 = m0 + mt * 16 + g;
            int c = n0 + j * 8 + tig * 2;
            __half2 lo = __floats2half2_rn(acc[mt][j].x, acc[mt][j].y);
            __half2 hi = __floats2half2_rn(acc[mt][j].z, acc[mt][j].w);
            *reinterpret_cast<uint*>(&Os[r1][c]) = *reinterpret_cast<uint*>(&lo);
            *reinterpret_cast<uint*>(&Os[r1 + 8][c]) = *reinterpret_cast<uint*>(&hi);
        }
    }
    __syncthreads();
#pragma unroll
    for (int i = 0; i < 8; i++) {
        int lin = tid + i * 256;
        int r = lin >> 4;
        int kc = (lin & 15) * 8;
        if (row0 + r < n)
            *reinterpret_cast<uint4*>(&g_H23h[(size_t)(row0 + r) * 256 + col0 + kc]) =
                *reinterpret_cast<const uint4*>(&Os[r][kc]);
    }
}

// ---------------------------------------------------------------------------
// GEMM2 (tensor core) fused with gated epilogue; smem-staged I/O.
// H2s/H3s rows padded to 72 halves (144B = 9*16B) so uint4 accesses stay aligned.
__global__ __launch_bounds__(256) void gemm2_mma(float* __restrict__ out, int n, int dup) {
    extern __shared__ char smem[];
    __half (*As)[136] = reinterpret_cast<__half(*)[136]>(smem);
    __half (*Bs)[136] = reinterpret_cast<__half(*)[136]>(smem + 34816);
    __half (*H2s)[72] = reinterpret_cast<__half(*)[72]>(smem + 34816);            // reuse Bs
    __half (*H3s)[72] = reinterpret_cast<__half(*)[72]>(smem + 34816 + 18432);
    float (*Os)[68]   = reinterpret_cast<float(*)[68]>(smem);                     // reuse As

    int tid = threadIdx.x;
    int row0 = blockIdx.y * 128;
    int col0 = blockIdx.x * 128;  // phys col in [0,256)
    int q0 = col0 >> 1;           // logical col base (0 or 64)

#pragma unroll
    for (int i = 0; i < 8; i++) {
        int lin = tid + i * 256;
        int r = lin >> 4;
        int kc = (lin & 15) * 8;
        uint4 v = make_uint4(0, 0, 0, 0);
        if (row0 + r < n)
            v = *reinterpret_cast<const uint4*>(&g_aggh[(size_t)(row0 + r) * 128 + kc]);
        *reinterpret_cast<uint4*>(&As[r][kc]) = v;
    }
#pragma unroll
    for (int i = 0; i < 8; i++) {
        int lin = tid + i * 256;
        int r = lin >> 4;
        int kc = (lin & 15) * 8;
        *reinterpret_cast<uint4*>(&Bs[r][kc]) =
            *reinterpret_cast<const uint4*>(&g_WcT[(size_t)(col0 + r) * 128 + kc]);
    }
    __syncthreads();

    int w = tid >> 5, lane = tid & 31;
    int g = lane >> 2, tig = lane & 3;
    int m0 = (w >> 1) * 32;
    int n0 = (w & 1) * 64;

    float4 acc[2][8];
#pragma unroll
    for (int mt = 0; mt < 2; mt++)
#pragma unroll
        for (int j = 0; j < 8; j++) acc[mt][j] = make_float4(0.f, 0.f, 0.f, 0.f);

#pragma unroll
    for (int kt = 0; kt < 128; kt += 16) {
        uint a[2][4];
#pragma unroll
        for (int mt = 0; mt < 2; mt++) {
            int mr = m0 + mt * 16 + g;
            a[mt][0] = *reinterpret_cast<const uint*>(&As[mr][kt + tig * 2]);
            a[mt][1] = *reinterpret_cast<const uint*>(&As[mr + 8][kt + tig * 2]);
            a[mt][2] = *reinterpret_cast<const uint*>(&As[mr][kt + tig * 2 + 8]);
            a[mt][3] = *reinterpret_cast<const uint*>(&As[mr + 8][kt + tig * 2 + 8]);
        }
#pragma unroll
        for (int j = 0; j < 8; j++) {
            int nc = n0 + j * 8 + g;
            uint b0 = *reinterpret_cast<const uint*>(&Bs[nc][kt + tig * 2]);
            uint b1 = *reinterpret_cast<const uint*>(&Bs[nc][kt + tig * 2 + 8]);
            mma16816(acc[0][j], a[0][0], a[0][1], a[0][2], a[0][3], b0, b1);
            mma16816(acc[1][j], a[1][0], a[1][1], a[1][2], a[1][3], b0, b1);
        }
    }
    __syncthreads();

    // Load H23 tile (coalesced) into smem: h2/h3 logical cols [q0, q0+64)
#pragma unroll
    for (int i = 0; i < 8; i++) {
        int lin = tid + i * 256;   // 2048 slots of 8 halves
        int a = lin >> 10;         // 0 = h2, 1 = h3
        int rem = lin & 1023;
        int r = rem >> 3;
        int c8 = (rem & 7) * 8;
        uint4 v = make_uint4(0, 0, 0, 0);
        if (row0 + r < n)
            v = *reinterpret_cast<const uint4*>(
                &g_H23h[(size_t)(row0 + r) * 256 + a * 128 + q0 + c8]);
        if (a == 0) *reinterpret_cast<uint4*>(&H2s[r][c8]) = v;
        else        *reinterpret_cast<uint4*>(&H3s[r][c8]) = v;
    }
    __syncthreads();

    // Epilogue into smem: phys pair (acc.x=f1, acc.y=f2) -> logical qloc
#pragma unroll
    for (int mt = 0; mt < 2; mt++) {
#pragma unroll
        for (int j = 0; j < 8; j++) {
            int r1 = m0 + mt * 16 + g;
            int r2 = r1 + 8;
            int qloc = (n0 >> 1) + j * 4 + tig;
            float h2a = __half2float(H2s[r1][qloc]);
            float h3a = __half2float(H3s[r1][qloc]);
            Os[r1][qloc] = h3a + fmaxf(acc[mt][j].x + h2a, 0.f) * acc[mt][j].y;
            float h2b = __half2float(H2s[r2][qloc]);
            float h3b = __half2float(H3s[r2][qloc]);
            Os[r2][qloc] = h3b + fmaxf(acc[mt][j].z + h2b, 0.f) * acc[mt][j].w;
        }
    }
    __syncthreads();

    // Coalesced store of 128 x 64 fp32 tile (+ duplicate half)
    size_t ndup = (size_t)n * 128;
#pragma unroll
    for (int i = 0; i < 8; i++) {
        int lin = tid + i * 256;   // 2048 float4 slots
        int r = lin >> 4;
        int c4 = (lin & 15) * 4;
        if (row0 + r < n) {
            float4 v = *reinterpret_cast<const float4*>(&Os[r][c4]);
            size_t off = (size_t)(row0 + r) * 128 + q0 + c4;
            *reinterpret_cast<float4*>(&out[off]) = v;
            if (dup) *reinterpret_cast<float4*>(&out[ndup + off]) = v;
        }
    }
}

// ---------------------------------------------------------------------------
extern "C" void kernel_launch(void* const* d_in, const int* in_sizes, int n_in,
                              void* d_out, int out_size) {
    const float* hidden = (const float*)d_in[0];
    const int*   src    = (const int*)d_in[1];
    const int*   dst    = (const int*)d_in[2];
    const float* W_h    = (const float*)d_in[3];
    const float* W_hf   = (const float*)d_in[4];
    float* out = (float*)d_out;

    int n = in_sizes[0] / 128;
    int e = in_sizes[1];
    int nb = (n + CHUNK - 1) / CHUNK;
    int dup = (out_size >= 2 * n * 128) ? 1 : 0;
    const int SMEM_G1 = 2 * 34816;                 // 69632
    const int SMEM_G2 = 34816 + 2 * (128 * 144);   // 71680

    // Lazy one-time resources (created on the non-captured correctness call).
    static cudaStream_t side = nullptr;
    static cudaEvent_t ev_fork = nullptr, ev_zero = nullptr, ev_join = nullptr;
    static int* p_outdeg = nullptr;
    static int* p_indeg = nullptr;
    if (side == nullptr) {
        cudaStreamCreateWithFlags(&side, cudaStreamNonBlocking);
        cudaEventCreateWithFlags(&ev_fork, cudaEventDisableTiming);
        cudaEventCreateWithFlags(&ev_zero, cudaEventDisableTiming);
        cudaEventCreateWithFlags(&ev_join, cudaEventDisableTiming);
        cudaGetSymbolAddress((void**)&p_outdeg, g_outdeg);
        cudaGetSymbolAddress((void**)&p_indeg, g_indeg);
        cudaFuncSetAttribute(gemm1_mma, cudaFuncAttributeMaxDynamicSharedMemorySize, SMEM_G1);
        cudaFuncSetAttribute(gemm2_mma, cudaFuncAttributeMaxDynamicSharedMemorySize, SMEM_G2);
    }

    // ---- fork ----
    cudaEventRecord(ev_fork, 0);
    cudaStreamWaitEvent(side, ev_fork, 0);
    wprep_kernel<<<128, 256, 0, side>>>(W_h, W_hf);   // WhT (gemm1) + WcT (gemm2)

    // main: zero degree arrays via memset, record for side's outdeg
    cudaMemsetAsync(p_outdeg, 0, (size_t)n * sizeof(int), 0);
    cudaMemsetAsync(p_indeg, 0, (size_t)n * sizeof(int), 0);
    cudaEventRecord(ev_zero, 0);

    // side: outdeg -> gemm1 (emits H23h + hsc)
    cudaStreamWaitEvent(side, ev_zero, 0);
    outdeg_kernel<<<(e / 4 + 255) / 256, 256, 0, side>>>(src, e);
    gemm1_mma<<<dim3(2, (n + 127) / 128), 256, SMEM_G1, side>>>(hidden, n);
    cudaEventRecord(ev_join, side);

    // main: indeg -> CSR build
    indeg_kernel<<<(e / 4 + 255) / 256, 256>>>(dst, e);
    chunk_reduce_kernel<<<nb, 256>>>(n);
    chunk_scan_kernel<<<nb, 256>>>(n, nb);
    fill_kernel<<<(e / 4 + 255) / 256, 256>>>(src, dst, e);

    // ---- join: gather needs hsc (gemm1) + csr; gemm2 needs WcT + H23h ----
    cudaStreamWaitEvent(0, ev_join, 0);
    gather_kernel<<<(n * 32 + 255) / 256, 256>>>(n);
    gemm2_mma<<<dim3(2, (n + 127) / 128), 256, SMEM_G2>>>(out, n, dup);
}